// round 17
// baseline (speedup 1.0000x reference)
#include <cuda_runtime.h>
#include <cuda_fp16.h>
#include <cstdint>
#include <math.h>

#define NBATCH 16
#define SEQ    1024
#define EMB    1024
#define NHEAD  16
#define HD     64
#define NTOK   (NBATCH*SEQ)   // 16384

// Scratch: tiled, pre-swizzled fp16 (hi-only; pure fp16 compute).
__device__ __half g_Xh[(size_t)NTOK*EMB];
__device__ __half g_Qh[(size_t)NTOK*EMB];   // pre-scaled by 0.03125*log2(e)
__device__ __half g_Kh[(size_t)NTOK*EMB];
__device__ __half g_Vh[(size_t)NTOK*EMB];
__device__ __half g_Oh[(size_t)NTOK*EMB];
__device__ __half g_Wq[(size_t)EMB*EMB];
__device__ __half g_Wk[(size_t)EMB*EMB];
__device__ __half g_Wv[(size_t)EMB*EMB];
__device__ __half g_Wo[(size_t)EMB*EMB];
__device__ uint32_t g_Mb[(size_t)NBATCH*SEQ*(SEQ/32)];   // mask bitpack, 2MB

#define QSCALE 0.04508422057676f   // 0.03125 * log2(e)

__device__ __forceinline__ uint32_t smem_u32(const void* p) {
    return (uint32_t)__cvta_generic_to_shared(p);
}
__device__ __forceinline__ uint32_t swz64(uint32_t o)  { return o ^ ((o >> 3) & 0x30); }
__device__ __forceinline__ uint32_t swz128(uint32_t o) { return o ^ ((o >> 3) & 0x70); }

#define LDSM4(r, addr) \
    asm volatile("ldmatrix.sync.aligned.m8n8.x4.shared.b16 {%0,%1,%2,%3}, [%4];" \
                 : "=r"((r)[0]), "=r"((r)[1]), "=r"((r)[2]), "=r"((r)[3]) : "r"(addr))
#define LDSM2(r, addr) \
    asm volatile("ldmatrix.sync.aligned.m8n8.x2.shared.b16 {%0,%1}, [%2];" \
                 : "=r"((r)[0]), "=r"((r)[1]) : "r"(addr))
#define LDSM2T(r, addr) \
    asm volatile("ldmatrix.sync.aligned.m8n8.x2.trans.shared.b16 {%0,%1}, [%2];" \
                 : "=r"((r)[0]), "=r"((r)[1]) : "r"(addr))
#define MMA16816(c, a, b) \
    asm volatile("mma.sync.aligned.m16n8k16.row.col.f32.f16.f16.f32 " \
                 "{%0,%1,%2,%3}, {%4,%5,%6,%7}, {%8,%9}, {%0,%1,%2,%3};" \
                 : "+f"((c)[0]), "+f"((c)[1]), "+f"((c)[2]), "+f"((c)[3]) \
                 : "r"((a)[0]), "r"((a)[1]), "r"((a)[2]), "r"((a)[3]), \
                   "r"((b)[0]), "r"((b)[1]))

#define BULK_G2S(dstS, srcG, bytes, mbar) \
    asm volatile("cp.async.bulk.shared::cluster.global.mbarrier::complete_tx::bytes " \
                 "[%0], [%1], %2, [%3];" \
                 :: "r"(dstS), "l"(srcG), "r"(bytes), "r"(mbar) : "memory")
#define MBAR_INIT(a, c) \
    asm volatile("mbarrier.init.shared.b64 [%0], %1;" :: "r"(a), "r"(c) : "memory")
#define MBAR_EXPECT(a, tx) \
    asm volatile("mbarrier.arrive.expect_tx.shared.b64 _, [%0], %1;" :: "r"(a), "r"(tx) : "memory")
#define MBAR_WAIT(a, ph) do { \
    uint32_t _done = 0; \
    while (!_done) { \
        asm volatile("{\n\t.reg .pred p;\n\t" \
            "mbarrier.try_wait.parity.acquire.cta.shared::cta.b64 p, [%1], %2, 0x989680;\n\t" \
            "selp.b32 %0, 1, 0, p;\n\t}" \
            : "=r"(_done) : "r"(a), "r"((uint32_t)(ph)) : "memory"); \
    } } while (0)

__device__ __forceinline__ uint32_t pack_h(float x, float y)
{
    __half2 t = __floats2half2_rn(x, y);
    return *reinterpret_cast<uint32_t*>(&t);
}

// ---------------------------------------------------------------------------
// Prep kernels.
// ---------------------------------------------------------------------------
__device__ __forceinline__ void conv_one(const float* __restrict__ src,
                                         __half* __restrict__ hi, int i)
{
    const int row  = i >> 7;
    const int colq = (i & 127) * 8;
    float4 v0 = *(const float4*)(src + (size_t)row*EMB + colq);
    float4 v1 = *(const float4*)(src + (size_t)row*EMB + colq + 4);
    uint32_t h0 = pack_h(v0.x, v0.y);
    uint32_t h1 = pack_h(v0.z, v0.w);
    uint32_t h2 = pack_h(v1.x, v1.y);
    uint32_t h3 = pack_h(v1.z, v1.w);
    const size_t blk = (size_t)((row >> 7)*32 + (colq >> 5)) * 8192;
    const uint32_t inner = swz64((uint32_t)((row & 127)*64 + (colq & 31)*2));
    *(uint4*)((char*)hi + blk + inner) = make_uint4(h0, h1, h2, h3);
}

__global__ __launch_bounds__(256)
void conv_x(const float* __restrict__ src, int total8)
{
    int i = blockIdx.x * 256 + threadIdx.x;
    if (i < total8) conv_one(src, g_Xh, i);
}

__global__ __launch_bounds__(256)
void conv_w(const float* __restrict__ Wq, const float* __restrict__ Wk,
            const float* __restrict__ Wv, const float* __restrict__ Wo, int total8)
{
    int i = blockIdx.x * 256 + threadIdx.x;
    if (i >= total8) return;
    const int z = blockIdx.z;
    const float* src = (z==0) ? Wq : (z==1) ? Wk : (z==2) ? Wv : Wo;
    __half* dst = (z==0) ? g_Wq : (z==1) ? g_Wk : (z==2) ? g_Wv : g_Wo;
    conv_one(src, dst, i);
}

__global__ __launch_bounds__(256)
void pack_mask(const int* __restrict__ mask, int total)
{
    int i = blockIdx.x * 256 + threadIdx.x;
    if (i >= total) return;
    const int* src = mask + (size_t)i * 32;
    uint32_t w = 0;
    #pragma unroll
    for (int j = 0; j < 32; j += 4) {
        int4 v = *(const int4*)(src + j);
        w |= (v.x ? 1u : 0u) << j;
        w |= (v.y ? 1u : 0u) << (j+1);
        w |= (v.z ? 1u : 0u) << (j+2);
        w |= (v.w ? 1u : 0u) << (j+3);
    }
    g_Mb[i] = w;
}

// ---------------------------------------------------------------------------
// GEMM core: 128x128 CTA tile, kstep 32, 8 warps (2M x 4N), 1-term fp16.
// 4-stage cp.async.bulk ring: each load has 3 compute iterations to land.
// ---------------------------------------------------------------------------
#define GNST   4
#define GSTAGE 16384
#define GEMM_SMEM (GNST*GSTAGE)   // 65536

__device__ __forceinline__ void gemm_load(
    uint32_t sb, uint32_t mba,
    const __half* gAh, const __half* gBh, int mblk, int nblk, int kb)
{
    MBAR_EXPECT(mba, 16384);
    BULK_G2S(sb,        (const char*)gAh + (size_t)(mblk*32+kb)*8192, 8192, mba);
    BULK_G2S(sb+8192,   (const char*)gBh + (size_t)(nblk*32+kb)*8192, 8192, mba);
}

__device__ __forceinline__ void gemm_main(
    const __half* gAh, const __half* gBh,
    int mblk, int nblk, float (&acc)[4][4][4])
{
    extern __shared__ char dsm[];
    __shared__ __align__(8) uint64_t mb[GNST];
    const int tid  = threadIdx.x;
    const int lane = tid & 31;
    const int warp = tid >> 5;
    const int wm   = warp >> 2;
    const int wn   = warp & 3;
    const uint32_t sal = smem_u32(dsm);

    #pragma unroll
    for (int i = 0; i < 4; i++)
        #pragma unroll
        for (int j = 0; j < 4; j++) {
            acc[i][j][0]=0.f; acc[i][j][1]=0.f; acc[i][j][2]=0.f; acc[i][j][3]=0.f;
        }

    if (tid == 0) {
        #pragma unroll
        for (int s = 0; s < GNST; s++) MBAR_INIT(smem_u32(&mb[s]), 1);
    }
    __syncthreads();

    if (tid == 0) {
        #pragma unroll
        for (int s = 0; s < GNST; s++)
            gemm_load(sal + s*GSTAGE, smem_u32(&mb[s]), gAh, gBh, mblk, nblk, s);
    }

    const int arow = wm*64 + (lane & 15);
    const uint32_t aby = (uint32_t)((lane >> 4) * 16);
    const int brow = wn*32 + (lane & 7);
    const uint32_t bby = (uint32_t)(((lane >> 3) & 1) * 16);

    for (int kt = 0; kt < 32; kt++) {
        const int s = kt & (GNST-1);
        MBAR_WAIT(smem_u32(&mb[s]), (kt >> 2) & 1);

        const uint32_t sAh = sal + s*GSTAGE;
        const uint32_t sBh = sAh + 8192;

        #pragma unroll
        for (int kh = 0; kh < 2; kh++) {
            uint32_t ah[4][4], bh2[4][2];
            #pragma unroll
            for (int mt = 0; mt < 4; mt++) {
                const uint32_t off = swz64((uint32_t)((arow + mt*16)*64) + kh*32 + aby);
                LDSM4(ah[mt], sAh + off);
            }
            #pragma unroll
            for (int nt = 0; nt < 4; nt++) {
                const uint32_t off = swz64((uint32_t)((brow + nt*8)*64) + kh*32 + bby);
                LDSM2(bh2[nt], sBh + off);
            }
            #pragma unroll
            for (int mt = 0; mt < 4; mt++)
                #pragma unroll
                for (int nt = 0; nt < 4; nt++)
                    MMA16816(acc[mt][nt], ah[mt], bh2[nt]);
        }
        __syncthreads();

        if (tid == 0 && kt + GNST < 32)
            gemm_load(sal + s*GSTAGE, smem_u32(&mb[s]), gAh, gBh, mblk, nblk, kt + GNST);
    }
}

// QKV projection: fp16 outputs, head-major SW128 blocks. Q pre-scaled.
__global__ __launch_bounds__(256, 2)
void gemm_qkv()
{
    const int bz = blockIdx.z;
    const __half* Wh = (bz==0) ? g_Wq : (bz==1) ? g_Wk : g_Wv;
    char* Ch = (char*)((bz==0) ? g_Qh : (bz==1) ? g_Kh : g_Vh);
    const float scl = (bz==0) ? QSCALE : 1.0f;

    float acc[4][4][4];
    gemm_main(g_Xh, Wh, blockIdx.y, blockIdx.x, acc);

    const int tid = threadIdx.x, lane = tid & 31, warp = tid >> 5;
    const int wm = warp >> 2, wn = warp & 3;
    const int g  = lane >> 2, tg = lane & 3;
    #pragma unroll
    for (int nt = 0; nt < 4; nt++) {
        const int col = blockIdx.x*128 + wn*32 + nt*8 + tg*2;
        const int h   = col >> 6;
        const int hc  = col & 63;
        #pragma unroll
        for (int mt = 0; mt < 4; mt++) {
            const int rowg = blockIdx.y*128 + wm*64 + mt*16 + g;
            const int b    = rowg >> 10;
            const int s_   = rowg & 1023;
            const size_t blk = (size_t)((b*16 + h)*8 + (s_ >> 7)) * 16384;
            const int srow = s_ & 127;
            *(uint32_t*)(Ch + blk + swz128((uint32_t)(srow*128 + hc*2)))
                = pack_h(acc[mt][nt][0]*scl, acc[mt][nt][1]*scl);
            *(uint32_t*)(Ch + blk + swz128((uint32_t)((srow+8)*128 + hc*2)))
                = pack_h(acc[mt][nt][2]*scl, acc[mt][nt][3]*scl);
        }
    }
}

// Output projection: fp32 out + bias.
__global__ __launch_bounds__(256, 2)
void gemm_out(const float* __restrict__ bias, float* __restrict__ C)
{
    float acc[4][4][4];
    gemm_main(g_Oh, g_Wo, blockIdx.y, blockIdx.x, acc);

    const int tid = threadIdx.x, lane = tid & 31, warp = tid >> 5;
    const int wm = warp >> 2, wn = warp & 3;
    const int g  = lane >> 2, tg = lane & 3;
    #pragma unroll
    for (int nt = 0; nt < 4; nt++) {
        const int col = blockIdx.x*128 + wn*32 + nt*8 + tg*2;
        const float b0 = bias[col], b1 = bias[col+1];
        #pragma unroll
        for (int mt = 0; mt < 4; mt++) {
            const int row0 = blockIdx.y*128 + wm*64 + mt*16 + g;
            *(float2*)(C + (size_t)row0*EMB + col) =
                make_float2(acc[mt][nt][0] + b0, acc[mt][nt][1] + b1);
            *(float2*)(C + (size_t)(row0+8)*EMB + col) =
                make_float2(acc[mt][nt][2] + b0, acc[mt][nt][3] + b1);
        }
    }
}

// ---------------------------------------------------------------------------
// Flash attention, fixed-base softmax; 3-stage K/V ring.
// ---------------------------------------------------------------------------
#define ANST   3
#define ASTAGE 32768
#define ATTN_SMEM (ANST*ASTAGE)   // 98304

__device__ __forceinline__ void attn_load(
    uint32_t sb, uint32_t mba, const char* gKh, const char* gVh, int kc)
{
    MBAR_EXPECT(mba, 32768);
    BULK_G2S(sb,         gKh + (size_t)kc*16384, 16384, mba);
    BULK_G2S(sb+16384,   gVh + (size_t)kc*16384, 16384, mba);
}

__global__ __launch_bounds__(256, 2)
void attn_mma()
{
    extern __shared__ char dsm[];
    __shared__ __align__(8) uint64_t mb[ANST];

    const int tid  = threadIdx.x;
    const int lane = tid & 31;
    const int wid  = tid >> 5;
    const int g    = lane >> 2;
    const int tg   = lane & 3;
    const int bh   = blockIdx.y;
    const int b    = bh >> 4;
    const int q0   = blockIdx.x * 128;
    const int qrow0 = q0 + wid*16 + g;
    const int qrow1 = qrow0 + 8;
    const uint32_t sal = smem_u32(dsm);

    const char* gKh = (const char*)g_Kh + (size_t)bh*8*16384;
    const char* gVh = (const char*)g_Vh + (size_t)bh*8*16384;
    const uint32_t* Mb = g_Mb + (size_t)b*SEQ*(SEQ/32);

    if (tid == 0) {
        #pragma unroll
        for (int s = 0; s < ANST; s++) MBAR_INIT(smem_u32(&mb[s]), 1);
    }
    __syncthreads();
    if (tid == 0) {
        #pragma unroll
        for (int s = 0; s < ANST; s++)
            attn_load(sal + s*ASTAGE, smem_u32(&mb[s]), gKh, gVh, s);
    }

    // Q fragments (pre-scaled to log2 domain)
    uint32_t qh[4][4];
    {
        const size_t qblk = ((size_t)bh*8 + (qrow0 >> 7)) * 16384;
        const int srow0 = qrow0 & 127;
        const char* Qh = (const char*)g_Qh + qblk;
        #pragma unroll
        for (int kt = 0; kt < 4; kt++) {
            const int d0 = kt*16 + tg*2;
            qh[kt][0] = *(const uint32_t*)(Qh + swz128((uint32_t)(srow0*128 + d0*2)));
            qh[kt][1] = *(const uint32_t*)(Qh + swz128((uint32_t)((srow0+8)*128 + d0*2)));
            qh[kt][2] = *(const uint32_t*)(Qh + swz128((uint32_t)(srow0*128 + (d0+8)*2)));
            qh[kt][3] = *(const uint32_t*)(Qh + swz128((uint32_t)((srow0+8)*128 + (d0+8)*2)));
        }
    }

    float l0 = 0.f, l1 = 0.f;
    float o[8][4];
    #pragma unroll
    for (int nt = 0; nt < 8; nt++) { o[nt][0]=0.f; o[nt][1]=0.f; o[nt][2]=0.f; o[nt][3]=0.f; }

    const int lrow8 = lane & 7;
    const int lk8   = ((lane >> 3) & 1) * 8;

    int s = 0, ph = 0;
    for (int kc = 0; kc < 8; kc++) {
        uint4 mq0 = *(const uint4*)(Mb + (size_t)qrow0*32 + kc*4);
        uint4 mq1 = *(const uint4*)(Mb + (size_t)qrow1*32 + kc*4);
        const uint32_t w0[4] = {mq0.x, mq0.y, mq0.z, mq0.w};
        const uint32_t w1[4] = {mq1.x, mq1.y, mq1.z, mq1.w};

        MBAR_WAIT(smem_u32(&mb[s]), ph);

        const uint32_t sKh = sal + s*ASTAGE;
        const uint32_t sVh = sKh + 16384;

        // ---- S, mask, exp2, sums, pack P ----
        uint32_t pah[8][4];
        #pragma unroll
        for (int nt = 0; nt < 16; nt++) {
            float ss[4];
            ss[0]=0.f; ss[1]=0.f; ss[2]=0.f; ss[3]=0.f;
            #pragma unroll
            for (int kt = 0; kt < 4; kt++) {
                uint32_t bh2[2];
                const uint32_t off = swz128((uint32_t)((nt*8 + lrow8)*128 + kt*32 + lk8*2));
                LDSM2(bh2, sKh + off);
                MMA16816(ss, qh[kt], bh2);
            }
            const int sh = (nt & 3)*8 + tg*2;
            const uint32_t b0m = w0[nt >> 2] >> sh;
            const uint32_t b1m = w1[nt >> 2] >> sh;
            float p0 = exp2f((b0m & 1u)        ? ss[0] : -1e30f);
            float p1 = exp2f(((b0m >> 1) & 1u) ? ss[1] : -1e30f);
            float p2 = exp2f((b1m & 1u)        ? ss[2] : -1e30f);
            float p3 = exp2f(((b1m >> 1) & 1u) ? ss[3] : -1e30f);
            l0 += p0 + p1;
            l1 += p2 + p3;
            const int kt  = nt >> 1;
            const int off = (nt & 1) * 2;
            pah[kt][off]   = pack_h(p0, p1);
            pah[kt][off+1] = pack_h(p2, p3);
        }

        // ---- O += P V (1-term) ----
        #pragma unroll
        for (int nt = 0; nt < 8; nt++) {
            #pragma unroll
            for (int kt = 0; kt < 8; kt++) {
                uint32_t vb2h[2];
                const uint32_t off = swz128((uint32_t)((kt*16 + lrow8 + lk8)*128 + nt*16));
                LDSM2T(vb2h, sVh + off);
                MMA16816(o[nt], pah[kt], vb2h);
            }
        }
        __syncthreads();

        if (tid == 0 && kc + ANST < 8)
            attn_load(sal + s*ASTAGE, smem_u32(&mb[s]), gKh, gVh, kc + ANST);

        if (++s == ANST) { s = 0; ph ^= 1; }
    }

    // single row-sum reduction
    l0 += __shfl_xor_sync(0xffffffffu, l0, 1);
    l0 += __shfl_xor_sync(0xffffffffu, l0, 2);
    l1 += __shfl_xor_sync(0xffffffffu, l1, 1);
    l1 += __shfl_xor_sync(0xffffffffu, l1, 2);

    // ---- normalize + write fp16 into out-proj A-tile layout ----
    const float inv0 = 1.0f / l0;
    const float inv1 = 1.0f / l1;
    const int h    = bh & 15;
    const int srow0 = qrow0 & 127;
    const int mblk  = (b*SEQ + qrow0) >> 7;
    #pragma unroll
    for (int nt = 0; nt < 8; nt++) {
        const int col  = h*64 + nt*8 + tg*2;
        const int kblk = col >> 5;
        const int cin  = col & 31;
        const size_t blk = (size_t)(mblk*32 + kblk) * 8192;
        *(uint32_t*)((char*)g_Oh + blk + swz64((uint32_t)(srow0*64 + cin*2)))
            = pack_h(o[nt][0]*inv0, o[nt][1]*inv0);
        *(uint32_t*)((char*)g_Oh + blk + swz64((uint32_t)((srow0+8)*64 + cin*2)))
            = pack_h(o[nt][2]*inv1, o[nt][3]*inv1);
    }
}

// ---------------------------------------------------------------------------
extern "C" void kernel_launch(void* const* d_in, const int* in_sizes, int n_in,
                              void* d_out, int out_size)
{
    const float* X    = (const float*)d_in[0];
    const int*   mask = (const int*)  d_in[1];
    const float* Wq   = (const float*)d_in[2];
    const float* Wk   = (const float*)d_in[3];
    const float* Wv   = (const float*)d_in[4];
    const float* Wo   = (const float*)d_in[5];
    const float* bo   = (const float*)d_in[6];
    float* out = (float*)d_out;

    cudaFuncSetAttribute(gemm_qkv,
                         cudaFuncAttributeMaxDynamicSharedMemorySize, GEMM_SMEM);
    cudaFuncSetAttribute(gemm_out,
                         cudaFuncAttributeMaxDynamicSharedMemorySize, GEMM_SMEM);
    cudaFuncSetAttribute(attn_mma,
                         cudaFuncAttributeMaxDynamicSharedMemorySize, ATTN_SMEM);

    dim3 blk(256);

    const int t8X = NTOK*EMB/8;
    const int t8W = EMB*EMB/8;
    const int tM  = NBATCH*SEQ*(SEQ/32);
    conv_x<<<(t8X+255)/256, blk>>>(X, t8X);
    conv_w<<<dim3((t8W+255)/256, 1, 4), blk>>>(Wq, Wk, Wv, Wo, t8W);
    pack_mask<<<(tM+255)/256, blk>>>(mask, tM);

    gemm_qkv<<<dim3(EMB/128, NTOK/128, 3), blk, GEMM_SMEM>>>();

    attn_mma<<<dim3(SEQ/128, NBATCH*NHEAD), blk, ATTN_SMEM>>>();

    gemm_out<<<dim3(EMB/128, NTOK/128), blk, GEMM_SMEM>>>(bo, out);
}